// round 2
// baseline (speedup 1.0000x reference)
#include <cuda_runtime.h>
#include <cuda_bf16.h>
#include <math_constants.h>

// Problem constants (fixed by the reference).
#define NN 50000
#define NE 800000
#define INC 128     // layer-1 in channels, also layer-2 in channels (2*64)
#define HC 128      // heads*hid = 128 channels after layer 1
#define OC 5        // output channels
#define NEG_SLOPE 0.2f

// ---------------- device scratch (no allocations allowed) ----------------
__device__ float g_xl[(size_t)NN * HC];    // x @ W1l + b1l
__device__ float g_xr[(size_t)NN * HC];    // x @ W1r + b1r
__device__ float g_h [(size_t)NN * HC];    // layer-1 output (after ELU)
__device__ float g_h2l[(size_t)NN * 8];    // h @ W2l + b2l (padded to 8)
__device__ float g_h2r[(size_t)NN * 8];    // h @ W2r + b2r (padded to 8)
__device__ int   g_counts[NN];
__device__ int   g_incl[NN + 1024];
__device__ int   g_off[NN + 1];
__device__ int   g_cursor[NN];
__device__ int   g_bsum[64];
__device__ int   g_eid[NE];

// ---------------- CSR build ----------------
__global__ void k_zero_counts() {
    int i = blockIdx.x * blockDim.x + threadIdx.x;
    if (i < NN) g_counts[i] = 0;
}

__global__ void k_hist(const int* __restrict__ dst) {
    int i = blockIdx.x * blockDim.x + threadIdx.x;
    if (i < NE) atomicAdd(&g_counts[dst[i]], 1);
}

// block-wise inclusive scan over counts (1024 per block)
__global__ void k_scan1() {
    __shared__ int s[1024];
    int t = threadIdx.x;
    int idx = blockIdx.x * 1024 + t;
    int v = (idx < NN) ? g_counts[idx] : 0;
    s[t] = v;
    __syncthreads();
    #pragma unroll
    for (int o = 1; o < 1024; o <<= 1) {
        int add = (t >= o) ? s[t - o] : 0;
        __syncthreads();
        s[t] += add;
        __syncthreads();
    }
    g_incl[idx] = s[t];
    if (t == 1023) g_bsum[blockIdx.x] = s[1023];
}

__global__ void k_scan2(int nblocks) {
    if (threadIdx.x == 0 && blockIdx.x == 0) {
        int run = 0;
        for (int b = 0; b < nblocks; b++) {
            int v = g_bsum[b];
            g_bsum[b] = run;
            run += v;
        }
    }
}

__global__ void k_scan3() {
    int i = blockIdx.x * blockDim.x + threadIdx.x;
    if (i < NN) {
        int incl = g_incl[i] + g_bsum[i / 1024];
        int excl = incl - g_counts[i];
        g_off[i] = excl;
        g_cursor[i] = excl;
        if (i == NN - 1) g_off[NN] = incl;
    }
}

__global__ void k_scatter(const int* __restrict__ dst) {
    int e = blockIdx.x * blockDim.x + threadIdx.x;
    if (e < NE) {
        int pos = atomicAdd(&g_cursor[dst[e]], 1);
        g_eid[pos] = e;
    }
}

// ---------------- GEMM: C[M,Nc] = A[M,128] @ B[128,Nc] + bias ----------------
// BM=64, BN=64, BK=32, 256 threads, 4x4 register tile per thread.
__global__ void k_gemm(const float* __restrict__ A, const float* __restrict__ B,
                       const float* __restrict__ bias, float* __restrict__ C,
                       int M, int Nc) {
    __shared__ float As[32][68];   // transposed: As[k][row]
    __shared__ float Bs[32][68];   // Bs[k][col]
    int tid = threadIdx.x;
    int tx = tid & 15, ty = tid >> 4;
    int rb = blockIdx.x * 64, cb = blockIdx.y * 64;
    float acc[4][4] = {};

    int lr = tid >> 3;       // 0..31 : A load row (first half)
    int lf = tid & 7;        // float4 index in k-chunk
    int bkr = tid >> 4;      // 0..15 : B load row
    int bcq = tid & 15;

    for (int k0 = 0; k0 < 128; k0 += 32) {
        #pragma unroll
        for (int h = 0; h < 2; h++) {
            int r = lr + 32 * h;
            int gr = rb + r;
            float4 v = make_float4(0.f, 0.f, 0.f, 0.f);
            if (gr < M) v = *(const float4*)(A + (size_t)gr * 128 + k0 + lf * 4);
            As[lf * 4 + 0][r] = v.x;
            As[lf * 4 + 1][r] = v.y;
            As[lf * 4 + 2][r] = v.z;
            As[lf * 4 + 3][r] = v.w;
        }
        #pragma unroll
        for (int h = 0; h < 2; h++) {
            int kr = bkr + 16 * h;
            float4 v = *(const float4*)(B + (size_t)(k0 + kr) * Nc + cb + bcq * 4);
            *(float4*)&Bs[kr][bcq * 4] = v;
        }
        __syncthreads();
        #pragma unroll
        for (int kk = 0; kk < 32; kk++) {
            float4 a = *(float4*)&As[kk][ty * 4];
            float4 b = *(float4*)&Bs[kk][tx * 4];
            float av[4] = {a.x, a.y, a.z, a.w};
            float bv[4] = {b.x, b.y, b.z, b.w};
            #pragma unroll
            for (int i = 0; i < 4; i++)
                #pragma unroll
                for (int j = 0; j < 4; j++)
                    acc[i][j] += av[i] * bv[j];
        }
        __syncthreads();
    }
    #pragma unroll
    for (int i = 0; i < 4; i++) {
        int gr = rb + ty * 4 + i;
        if (gr < M) {
            #pragma unroll
            for (int j = 0; j < 4; j++) {
                int gc = cb + tx * 4 + j;
                C[(size_t)gr * Nc + gc] = acc[i][j] + bias[gc];
            }
        }
    }
}

// ---------------- Layer-1 edge phase: warp per destination node ----------------
// online segment softmax + message aggregation, fused with +bias1 and ELU.
__global__ void k_edge1(const int* __restrict__ src, const float* __restrict__ eattr,
                        const float* __restrict__ att1, const float* __restrict__ W1e,
                        const float* __restrict__ b1e, const float* __restrict__ bias1) {
    int gw = (blockIdx.x * blockDim.x + threadIdx.x) >> 5;
    int lane = threadIdx.x & 31;
    if (gw >= NN) return;
    int n = gw;

    // lane channels: c0=lane, c1=lane+32 (head 0); c2=lane+64, c3=lane+96 (head 1)
    float xr0 = g_xr[(size_t)n * 128 + lane];
    float xr1 = g_xr[(size_t)n * 128 + lane + 32];
    float xr2 = g_xr[(size_t)n * 128 + lane + 64];
    float xr3 = g_xr[(size_t)n * 128 + lane + 96];
    float a0 = __ldg(&att1[lane]),      a1 = __ldg(&att1[lane + 32]);
    float a2 = __ldg(&att1[lane + 64]), a3 = __ldg(&att1[lane + 96]);
    float we0 = __ldg(&W1e[lane]),      we1 = __ldg(&W1e[lane + 32]);
    float we2 = __ldg(&W1e[lane + 64]), we3 = __ldg(&W1e[lane + 96]);
    float be0 = __ldg(&b1e[lane]),      be1 = __ldg(&b1e[lane + 32]);
    float be2 = __ldg(&b1e[lane + 64]), be3 = __ldg(&b1e[lane + 96]);

    int start = g_off[n], end = g_off[n + 1];

    float m0 = -CUDART_INF_F, m1 = -CUDART_INF_F;
    float d0 = 0.f, d1 = 0.f;
    float A0 = 0.f, A1 = 0.f, A2 = 0.f, A3 = 0.f;

    int s_cur = 0; float ea_cur = 0.f;
    if (start < end) {
        int e = __ldg(&g_eid[start]);
        s_cur = __ldg(&src[e]);
        ea_cur = __ldg(&eattr[e]);
    }
    for (int i = start; i < end; i++) {
        int s = s_cur; float ea = ea_cur;
        if (i + 1 < end) {                       // prefetch next edge indices
            int e2 = __ldg(&g_eid[i + 1]);
            s_cur = __ldg(&src[e2]);
            ea_cur = __ldg(&eattr[e2]);
        }
        size_t base = (size_t)s * 128 + lane;
        float x0 = g_xl[base];
        float x1 = g_xl[base + 32];
        float x2 = g_xl[base + 64];
        float x3 = g_xl[base + 96];
        float t0 = x0 + xr0 + ea * we0 + be0;
        float t1 = x1 + xr1 + ea * we1 + be1;
        float t2 = x2 + xr2 + ea * we2 + be2;
        float t3 = x3 + xr3 + ea * we3 + be3;
        t0 = t0 > 0.f ? t0 : NEG_SLOPE * t0;
        t1 = t1 > 0.f ? t1 : NEG_SLOPE * t1;
        t2 = t2 > 0.f ? t2 : NEG_SLOPE * t2;
        t3 = t3 > 0.f ? t3 : NEG_SLOPE * t3;
        float p0 = t0 * a0 + t1 * a1;
        float p1 = t2 * a2 + t3 * a3;
        #pragma unroll
        for (int o = 16; o > 0; o >>= 1) {
            p0 += __shfl_xor_sync(0xffffffffu, p0, o);
            p1 += __shfl_xor_sync(0xffffffffu, p1, o);
        }
        // online softmax, head 0
        {
            float nm = fmaxf(m0, p0);
            float corr = __expf(m0 - nm);
            float w = __expf(p0 - nm);
            d0 = d0 * corr + w;
            A0 = A0 * corr + w * x0;
            A1 = A1 * corr + w * x1;
            m0 = nm;
        }
        // head 1
        {
            float nm = fmaxf(m1, p1);
            float corr = __expf(m1 - nm);
            float w = __expf(p1 - nm);
            d1 = d1 * corr + w;
            A2 = A2 * corr + w * x2;
            A3 = A3 * corr + w * x3;
            m1 = nm;
        }
    }
    float o0 = (d0 > 0.f) ? A0 / d0 : 0.f;
    float o1 = (d0 > 0.f) ? A1 / d0 : 0.f;
    float o2 = (d1 > 0.f) ? A2 / d1 : 0.f;
    float o3 = (d1 > 0.f) ? A3 / d1 : 0.f;
    o0 += __ldg(&bias1[lane]);
    o1 += __ldg(&bias1[lane + 32]);
    o2 += __ldg(&bias1[lane + 64]);
    o3 += __ldg(&bias1[lane + 96]);
    // ELU
    o0 = o0 > 0.f ? o0 : (__expf(o0) - 1.f);
    o1 = o1 > 0.f ? o1 : (__expf(o1) - 1.f);
    o2 = o2 > 0.f ? o2 : (__expf(o2) - 1.f);
    o3 = o3 > 0.f ? o3 : (__expf(o3) - 1.f);
    g_h[(size_t)n * 128 + lane]      = o0;
    g_h[(size_t)n * 128 + lane + 32] = o1;
    g_h[(size_t)n * 128 + lane + 64] = o2;
    g_h[(size_t)n * 128 + lane + 96] = o3;
}

// ---------------- Layer-2 node transforms: h2l, h2r (warp per node) ----------------
__global__ void k_l2t(const float* __restrict__ W2l, const float* __restrict__ b2l,
                      const float* __restrict__ W2r, const float* __restrict__ b2r) {
    __shared__ float sWl[128 * 5], sWr[128 * 5], sbl[5], sbr[5];
    int tid = threadIdx.x;
    for (int i = tid; i < 640; i += blockDim.x) { sWl[i] = W2l[i]; sWr[i] = W2r[i]; }
    if (tid < 5) { sbl[tid] = b2l[tid]; sbr[tid] = b2r[tid]; }
    __syncthreads();
    int gw = (blockIdx.x * blockDim.x + tid) >> 5;
    int lane = tid & 31;
    if (gw >= NN) return;
    float hv[4];
    size_t base = (size_t)gw * 128 + lane;
    #pragma unroll
    for (int j = 0; j < 4; j++) hv[j] = g_h[base + 32 * j];
    float rl[5], rr[5];
    #pragma unroll
    for (int c = 0; c < 5; c++) {
        float pl = 0.f, pr = 0.f;
        #pragma unroll
        for (int j = 0; j < 4; j++) {
            int k = lane + 32 * j;
            pl += hv[j] * sWl[k * 5 + c];
            pr += hv[j] * sWr[k * 5 + c];
        }
        #pragma unroll
        for (int o = 16; o > 0; o >>= 1) {
            pl += __shfl_xor_sync(0xffffffffu, pl, o);
            pr += __shfl_xor_sync(0xffffffffu, pr, o);
        }
        rl[c] = pl; rr[c] = pr;
    }
    if (lane == 0) {
        #pragma unroll
        for (int c = 0; c < 5; c++) {
            g_h2l[(size_t)gw * 8 + c] = rl[c] + sbl[c];
            g_h2r[(size_t)gw * 8 + c] = rr[c] + sbr[c];
        }
        #pragma unroll
        for (int c = 5; c < 8; c++) {
            g_h2l[(size_t)gw * 8 + c] = 0.f;
            g_h2r[(size_t)gw * 8 + c] = 0.f;
        }
    }
}

// ---------------- Layer-2 edge phase: warp per node, lanes over edges ----------------
__global__ void k_edge2(const int* __restrict__ src, const float* __restrict__ eattr,
                        const float* __restrict__ W2e, const float* __restrict__ b2e,
                        const float* __restrict__ att2, const float* __restrict__ bias2,
                        float* __restrict__ out) {
    int gw = (blockIdx.x * blockDim.x + threadIdx.x) >> 5;
    int lane = threadIdx.x & 31;
    if (gw >= NN) return;
    int n = gw;

    float xr[5], a2[5], we[5], be[5];
    #pragma unroll
    for (int c = 0; c < 5; c++) {
        xr[c] = g_h2r[(size_t)n * 8 + c];
        a2[c] = __ldg(&att2[c]);
        we[c] = __ldg(&W2e[c]);
        be[c] = __ldg(&b2e[c]);
    }
    int off0 = g_off[n];
    int deg = g_off[n + 1] - off0;

    // pass 1: max logit
    float m = -CUDART_INF_F;
    for (int i = lane; i < deg; i += 32) {
        int e = __ldg(&g_eid[off0 + i]);
        int s = __ldg(&src[e]);
        float ea = __ldg(&eattr[e]);
        const float* xl = &g_h2l[(size_t)s * 8];
        float lg = 0.f;
        #pragma unroll
        for (int c = 0; c < 5; c++) {
            float t = xl[c] + xr[c] + ea * we[c] + be[c];
            t = t > 0.f ? t : NEG_SLOPE * t;
            lg += a2[c] * t;
        }
        m = fmaxf(m, lg);
    }
    #pragma unroll
    for (int o = 16; o > 0; o >>= 1)
        m = fmaxf(m, __shfl_xor_sync(0xffffffffu, m, o));

    // pass 2: weighted sums
    float d = 0.f, ac[5] = {0.f, 0.f, 0.f, 0.f, 0.f};
    for (int i = lane; i < deg; i += 32) {
        int e = __ldg(&g_eid[off0 + i]);
        int s = __ldg(&src[e]);
        float ea = __ldg(&eattr[e]);
        const float* xl = &g_h2l[(size_t)s * 8];
        float lg = 0.f;
        float xlv[5];
        #pragma unroll
        for (int c = 0; c < 5; c++) {
            xlv[c] = xl[c];
            float t = xlv[c] + xr[c] + ea * we[c] + be[c];
            t = t > 0.f ? t : NEG_SLOPE * t;
            lg += a2[c] * t;
        }
        float w = __expf(lg - m);
        d += w;
        #pragma unroll
        for (int c = 0; c < 5; c++) ac[c] += w * xlv[c];
    }
    #pragma unroll
    for (int o = 16; o > 0; o >>= 1) {
        d += __shfl_xor_sync(0xffffffffu, d, o);
        #pragma unroll
        for (int c = 0; c < 5; c++) ac[c] += __shfl_xor_sync(0xffffffffu, ac[c], o);
    }
    if (lane == 0) {
        #pragma unroll
        for (int c = 0; c < 5; c++) {
            float v = (d > 0.f) ? ac[c] / d : 0.f;
            out[(size_t)n * 5 + c] = v + __ldg(&bias2[c]);
        }
    }
}

// ---------------- launch ----------------
extern "C" void kernel_launch(void* const* d_in, const int* in_sizes, int n_in,
                              void* d_out, int out_size) {
    const float* x     = (const float*)d_in[0];
    const int*   eidx  = (const int*)d_in[1];
    const float* eattr = (const float*)d_in[2];
    const float* W1l   = (const float*)d_in[3];
    const float* b1l   = (const float*)d_in[4];
    const float* W1r   = (const float*)d_in[5];
    const float* b1r   = (const float*)d_in[6];
    const float* W1e   = (const float*)d_in[7];
    const float* b1e   = (const float*)d_in[8];
    const float* att1  = (const float*)d_in[9];
    const float* bias1 = (const float*)d_in[10];
    const float* W2l   = (const float*)d_in[11];
    const float* b2l   = (const float*)d_in[12];
    const float* W2r   = (const float*)d_in[13];
    const float* b2r   = (const float*)d_in[14];
    const float* W2e   = (const float*)d_in[15];
    const float* b2e   = (const float*)d_in[16];
    const float* att2  = (const float*)d_in[17];
    const float* bias2 = (const float*)d_in[18];
    float* out = (float*)d_out;

    const int* src = eidx;
    const int* dst = eidx + NE;

    float* gxl; cudaGetSymbolAddress((void**)&gxl, g_xl);
    float* gxr; cudaGetSymbolAddress((void**)&gxr, g_xr);

    // CSR build (dst)
    k_zero_counts<<<(NN + 255) / 256, 256>>>();
    k_hist<<<(NE + 255) / 256, 256>>>(dst);
    int nsb = (NN + 1023) / 1024;
    k_scan1<<<nsb, 1024>>>();
    k_scan2<<<1, 32>>>(nsb);
    k_scan3<<<(NN + 255) / 256, 256>>>();
    k_scatter<<<(NE + 255) / 256, 256>>>(dst);

    // layer-1 node transforms
    dim3 gg((NN + 63) / 64, 2);
    k_gemm<<<gg, 256>>>(x, W1l, b1l, gxl, NN, 128);
    k_gemm<<<gg, 256>>>(x, W1r, b1r, gxr, NN, 128);

    // layer-1 edge aggregation + ELU
    int nwb = (NN * 32 + 255) / 256;
    k_edge1<<<nwb, 256>>>(src, eattr, att1, W1e, b1e, bias1);

    // layer-2 node transforms + edge aggregation
    k_l2t<<<nwb, 256>>>(W2l, b2l, W2r, b2r);
    k_edge2<<<nwb, 256>>>(src, eattr, W2e, b2e, att2, bias2, out);

    (void)in_sizes; (void)n_in; (void)out_size;
}

// round 4
// speedup vs baseline: 1.1080x; 1.1080x over previous
#include <cuda_runtime.h>
#include <cuda_bf16.h>
#include <math_constants.h>

#define NN 50000
#define NE 800000
#define NEG_SLOPE 0.2f

// ---------------- device scratch ----------------
__device__ float g_xl[(size_t)NN * 128];   // x @ W1l + b1l
__device__ float g_xr[(size_t)NN * 128];   // x @ W1r + b1r
__device__ float g_h2l[(size_t)NN * 8];    // h @ W2l + b2l (stride 8)
__device__ float g_h2r[(size_t)NN * 8];    // h @ W2r + b2r (stride 8)
__device__ int   g_counts[NN];
__device__ int   g_incl[NN + 1024];
__device__ int   g_off[NN + 1];
__device__ int   g_cursor[NN];
__device__ int   g_bsum[64];
__device__ int   g_eid[NE];

// ---------------- CSR build ----------------
__global__ void k_hist(const int* __restrict__ dst) {
    int i = blockIdx.x * blockDim.x + threadIdx.x;
    if (i < NE) atomicAdd(&g_counts[dst[i]], 1);
}

__global__ void k_scan1() {
    __shared__ int s[1024];
    int t = threadIdx.x;
    int idx = blockIdx.x * 1024 + t;
    int v = (idx < NN) ? g_counts[idx] : 0;
    s[t] = v;
    __syncthreads();
    #pragma unroll
    for (int o = 1; o < 1024; o <<= 1) {
        int add = (t >= o) ? s[t - o] : 0;
        __syncthreads();
        s[t] += add;
        __syncthreads();
    }
    g_incl[idx] = s[t];
    if (t == 1023) g_bsum[blockIdx.x] = s[1023];
}

// parallel exclusive scan of <=64 block sums
__global__ void k_scan2(int nblocks) {
    __shared__ int s[64];
    int t = threadIdx.x;
    int v = (t < nblocks) ? g_bsum[t] : 0;
    s[t] = v;
    __syncthreads();
    #pragma unroll
    for (int o = 1; o < 64; o <<= 1) {
        int add = (t >= o) ? s[t - o] : 0;
        __syncthreads();
        s[t] += add;
        __syncthreads();
    }
    if (t < nblocks) g_bsum[t] = s[t] - v;   // exclusive
}

__global__ void k_scan3() {
    int i = blockIdx.x * blockDim.x + threadIdx.x;
    if (i < NN) {
        int incl = g_incl[i] + g_bsum[i / 1024];
        int excl = incl - g_counts[i];
        g_off[i] = excl;
        g_cursor[i] = excl;
        if (i == NN - 1) g_off[NN] = incl;
    }
}

__global__ void k_scatter(const int* __restrict__ dst) {
    int e = blockIdx.x * blockDim.x + threadIdx.x;
    if (e < NE) {
        int pos = atomicAdd(&g_cursor[dst[e]], 1);
        g_eid[pos] = e;
    }
}

// ---------------- fused dual GEMM: Cl = A@Bl+bl, Cr = A@Br+br ----------------
// A [M,128], B [128,128]. BM=64, BN=64, BK=32, 256 threads, 4x4 x2 register tiles.
__global__ void k_gemm2(const float* __restrict__ A,
                        const float* __restrict__ Bl, const float* __restrict__ bl,
                        const float* __restrict__ Br, const float* __restrict__ br,
                        float* __restrict__ Cl, float* __restrict__ Cr, int M) {
    __shared__ float As [32][68];   // As[k][row]
    __shared__ float Bsl[32][68];   // Bs[k][col]
    __shared__ float Bsr[32][68];
    int tid = threadIdx.x;
    int tx = tid & 15, ty = tid >> 4;
    int rb = blockIdx.x * 64, cb = blockIdx.y * 64;
    float accl[4][4] = {}, accr[4][4] = {};

    int lr = tid >> 3;       // 0..31 A row (first half)
    int lf = tid & 7;        // float4 index within 32-wide k chunk
    int bkr = tid >> 4;      // 0..15 B k-row
    int bcq = tid & 15;

    for (int k0 = 0; k0 < 128; k0 += 32) {
        #pragma unroll
        for (int h = 0; h < 2; h++) {
            int r = lr + 32 * h;
            int gr = rb + r;
            float4 v = make_float4(0.f, 0.f, 0.f, 0.f);
            if (gr < M) v = *(const float4*)(A + (size_t)gr * 128 + k0 + lf * 4);
            As[lf * 4 + 0][r] = v.x;
            As[lf * 4 + 1][r] = v.y;
            As[lf * 4 + 2][r] = v.z;
            As[lf * 4 + 3][r] = v.w;
        }
        #pragma unroll
        for (int h = 0; h < 2; h++) {
            int kr = bkr + 16 * h;
            *(float4*)&Bsl[kr][bcq * 4] = *(const float4*)(Bl + (size_t)(k0 + kr) * 128 + cb + bcq * 4);
            *(float4*)&Bsr[kr][bcq * 4] = *(const float4*)(Br + (size_t)(k0 + kr) * 128 + cb + bcq * 4);
        }
        __syncthreads();
        #pragma unroll
        for (int kk = 0; kk < 32; kk++) {
            float4 a  = *(float4*)&As [kk][ty * 4];
            float4 vl = *(float4*)&Bsl[kk][tx * 4];
            float4 vr = *(float4*)&Bsr[kk][tx * 4];
            float av[4] = {a.x, a.y, a.z, a.w};
            float blv[4] = {vl.x, vl.y, vl.z, vl.w};
            float brv[4] = {vr.x, vr.y, vr.z, vr.w};
            #pragma unroll
            for (int i = 0; i < 4; i++)
                #pragma unroll
                for (int j = 0; j < 4; j++) {
                    accl[i][j] += av[i] * blv[j];
                    accr[i][j] += av[i] * brv[j];
                }
        }
        __syncthreads();
    }
    #pragma unroll
    for (int i = 0; i < 4; i++) {
        int gr = rb + ty * 4 + i;
        if (gr < M) {
            #pragma unroll
            for (int j = 0; j < 4; j++) {
                int gc = cb + tx * 4 + j;
                Cl[(size_t)gr * 128 + gc] = accl[i][j] + bl[gc];
                Cr[(size_t)gr * 128 + gc] = accr[i][j] + br[gc];
            }
        }
    }
}

// ---------------- Layer-1 edge phase + ELU + layer-2 node transforms ----------------
// warp per destination node; never materializes h.
__global__ void k_edge1(const int* __restrict__ src, const float* __restrict__ eattr,
                        const float* __restrict__ att1, const float* __restrict__ W1e,
                        const float* __restrict__ b1e, const float* __restrict__ bias1,
                        const float* __restrict__ W2l, const float* __restrict__ b2l,
                        const float* __restrict__ W2r, const float* __restrict__ b2r) {
    __shared__ float sWl[128 * 5], sWr[128 * 5];
    int tid = threadIdx.x;
    for (int i = tid; i < 640; i += blockDim.x) { sWl[i] = W2l[i]; sWr[i] = W2r[i]; }
    __syncthreads();

    int gw = (blockIdx.x * blockDim.x + tid) >> 5;
    int lane = tid & 31;
    if (gw >= NN) return;
    int n = gw;

    float xr0 = g_xr[(size_t)n * 128 + lane];
    float xr1 = g_xr[(size_t)n * 128 + lane + 32];
    float xr2 = g_xr[(size_t)n * 128 + lane + 64];
    float xr3 = g_xr[(size_t)n * 128 + lane + 96];
    float a0 = __ldg(&att1[lane]),      a1 = __ldg(&att1[lane + 32]);
    float a2 = __ldg(&att1[lane + 64]), a3 = __ldg(&att1[lane + 96]);
    float we0 = __ldg(&W1e[lane]),      we1 = __ldg(&W1e[lane + 32]);
    float we2 = __ldg(&W1e[lane + 64]), we3 = __ldg(&W1e[lane + 96]);
    float be0 = __ldg(&b1e[lane]),      be1 = __ldg(&b1e[lane + 32]);
    float be2 = __ldg(&b1e[lane + 64]), be3 = __ldg(&b1e[lane + 96]);

    int start = g_off[n], end = g_off[n + 1];

    float m0 = -CUDART_INF_F, m1 = -CUDART_INF_F;
    float d0 = 0.f, d1 = 0.f;
    float A0 = 0.f, A1 = 0.f, A2 = 0.f, A3 = 0.f;

    int s_cur = 0; float ea_cur = 0.f;
    if (start < end) {
        int e = __ldg(&g_eid[start]);
        s_cur = __ldg(&src[e]);
        ea_cur = __ldg(&eattr[e]);
    }
    for (int i = start; i < end; i++) {
        int s = s_cur; float ea = ea_cur;
        if (i + 1 < end) {
            int e2 = __ldg(&g_eid[i + 1]);
            s_cur = __ldg(&src[e2]);
            ea_cur = __ldg(&eattr[e2]);
        }
        size_t base = (size_t)s * 128 + lane;
        float x0 = g_xl[base];
        float x1 = g_xl[base + 32];
        float x2 = g_xl[base + 64];
        float x3 = g_xl[base + 96];
        float t0 = x0 + xr0 + ea * we0 + be0;
        float t1 = x1 + xr1 + ea * we1 + be1;
        float t2 = x2 + xr2 + ea * we2 + be2;
        float t3 = x3 + xr3 + ea * we3 + be3;
        t0 = t0 > 0.f ? t0 : NEG_SLOPE * t0;
        t1 = t1 > 0.f ? t1 : NEG_SLOPE * t1;
        t2 = t2 > 0.f ? t2 : NEG_SLOPE * t2;
        t3 = t3 > 0.f ? t3 : NEG_SLOPE * t3;
        float p0 = t0 * a0 + t1 * a1;
        float p1 = t2 * a2 + t3 * a3;
        #pragma unroll
        for (int o = 16; o > 0; o >>= 1) {
            p0 += __shfl_xor_sync(0xffffffffu, p0, o);
            p1 += __shfl_xor_sync(0xffffffffu, p1, o);
        }
        {
            float nm = fmaxf(m0, p0);
            float corr = __expf(m0 - nm);
            float w = __expf(p0 - nm);
            d0 = d0 * corr + w;
            A0 = A0 * corr + w * x0;
            A1 = A1 * corr + w * x1;
            m0 = nm;
        }
        {
            float nm = fmaxf(m1, p1);
            float corr = __expf(m1 - nm);
            float w = __expf(p1 - nm);
            d1 = d1 * corr + w;
            A2 = A2 * corr + w * x2;
            A3 = A3 * corr + w * x3;
            m1 = nm;
        }
    }
    float o0 = (d0 > 0.f) ? A0 / d0 : 0.f;
    float o1 = (d0 > 0.f) ? A1 / d0 : 0.f;
    float o2 = (d1 > 0.f) ? A2 / d1 : 0.f;
    float o3 = (d1 > 0.f) ? A3 / d1 : 0.f;
    o0 += __ldg(&bias1[lane]);
    o1 += __ldg(&bias1[lane + 32]);
    o2 += __ldg(&bias1[lane + 64]);
    o3 += __ldg(&bias1[lane + 96]);
    // ELU -> h channels (lane, lane+32, lane+64, lane+96)
    o0 = o0 > 0.f ? o0 : (__expf(o0) - 1.f);
    o1 = o1 > 0.f ? o1 : (__expf(o1) - 1.f);
    o2 = o2 > 0.f ? o2 : (__expf(o2) - 1.f);
    o3 = o3 > 0.f ? o3 : (__expf(o3) - 1.f);

    // layer-2 node transforms: h2l = h@W2l+b2l, h2r = h@W2r+b2r (5 channels each)
    float hv[4] = {o0, o1, o2, o3};
    #pragma unroll
    for (int c = 0; c < 5; c++) {
        float pl = 0.f, pr = 0.f;
        #pragma unroll
        for (int j = 0; j < 4; j++) {
            int k = lane + 32 * j;
            pl += hv[j] * sWl[k * 5 + c];
            pr += hv[j] * sWr[k * 5 + c];
        }
        #pragma unroll
        for (int o = 16; o > 0; o >>= 1) {
            pl += __shfl_xor_sync(0xffffffffu, pl, o);
            pr += __shfl_xor_sync(0xffffffffu, pr, o);
        }
        if (lane == 0) {
            g_h2l[(size_t)n * 8 + c] = pl + __ldg(&b2l[c]);
            g_h2r[(size_t)n * 8 + c] = pr + __ldg(&b2r[c]);
        }
    }
}

// ---------------- Layer-2 edge phase: warp per node, single-pass online softmax ----
__global__ void k_edge2(const int* __restrict__ src, const float* __restrict__ eattr,
                        const float* __restrict__ W2e, const float* __restrict__ b2e,
                        const float* __restrict__ att2, const float* __restrict__ bias2,
                        float* __restrict__ out) {
    int gw = (blockIdx.x * blockDim.x + threadIdx.x) >> 5;
    int lane = threadIdx.x & 31;
    if (gw >= NN) return;
    int n = gw;

    float xr[5], a2[5], we[5], be[5];
    #pragma unroll
    for (int c = 0; c < 5; c++) {
        xr[c] = g_h2r[(size_t)n * 8 + c];
        a2[c] = __ldg(&att2[c]);
        we[c] = __ldg(&W2e[c]);
        be[c] = __ldg(&b2e[c]);
    }
    int off0 = g_off[n];
    int deg = g_off[n + 1] - off0;

    // per-lane online softmax
    float m = -CUDART_INF_F, d = 0.f, ac[5] = {0.f, 0.f, 0.f, 0.f, 0.f};
    for (int i = lane; i < deg; i += 32) {
        int e = __ldg(&g_eid[off0 + i]);
        int s = __ldg(&src[e]);
        float ea = __ldg(&eattr[e]);
        const float* xl = &g_h2l[(size_t)s * 8];
        float lg = 0.f, xlv[5];
        #pragma unroll
        for (int c = 0; c < 5; c++) {
            xlv[c] = xl[c];
            float t = xlv[c] + xr[c] + ea * we[c] + be[c];
            t = t > 0.f ? t : NEG_SLOPE * t;
            lg += a2[c] * t;
        }
        float nm = fmaxf(m, lg);
        float corr = __expf(m - nm);
        float w = __expf(lg - nm);
        d = d * corr + w;
        #pragma unroll
        for (int c = 0; c < 5; c++) ac[c] = ac[c] * corr + w * xlv[c];
        m = nm;
    }
    // combine lanes: global max, rescale, sum
    float M = m;
    #pragma unroll
    for (int o = 16; o > 0; o >>= 1)
        M = fmaxf(M, __shfl_xor_sync(0xffffffffu, M, o));
    float sc = (m == -CUDART_INF_F) ? 0.f : __expf(m - M);
    d *= sc;
    #pragma unroll
    for (int c = 0; c < 5; c++) ac[c] *= sc;
    #pragma unroll
    for (int o = 16; o > 0; o >>= 1) {
        d += __shfl_xor_sync(0xffffffffu, d, o);
        #pragma unroll
        for (int c = 0; c < 5; c++) ac[c] += __shfl_xor_sync(0xffffffffu, ac[c], o);
    }
    if (lane == 0) {
        #pragma unroll
        for (int c = 0; c < 5; c++) {
            float v = (d > 0.f) ? ac[c] / d : 0.f;
            out[(size_t)n * 5 + c] = v + __ldg(&bias2[c]);
        }
    }
}

// ---------------- launch ----------------
extern "C" void kernel_launch(void* const* d_in, const int* in_sizes, int n_in,
                              void* d_out, int out_size) {
    const float* x     = (const float*)d_in[0];
    const int*   eidx  = (const int*)d_in[1];
    const float* eattr = (const float*)d_in[2];
    const float* W1l   = (const float*)d_in[3];
    const float* b1l   = (const float*)d_in[4];
    const float* W1r   = (const float*)d_in[5];
    const float* b1r   = (const float*)d_in[6];
    const float* W1e   = (const float*)d_in[7];
    const float* b1e   = (const float*)d_in[8];
    const float* att1  = (const float*)d_in[9];
    const float* bias1 = (const float*)d_in[10];
    const float* W2l   = (const float*)d_in[11];
    const float* b2l   = (const float*)d_in[12];
    const float* W2r   = (const float*)d_in[13];
    const float* b2r   = (const float*)d_in[14];
    const float* W2e   = (const float*)d_in[15];
    const float* b2e   = (const float*)d_in[16];
    const float* att2  = (const float*)d_in[17];
    const float* bias2 = (const float*)d_in[18];
    float* out = (float*)d_out;

    const int* src = eidx;
    const int* dst = eidx + NE;

    float* gxl; cudaGetSymbolAddress((void**)&gxl, g_xl);
    float* gxr; cudaGetSymbolAddress((void**)&gxr, g_xr);
    int* gcnt;  cudaGetSymbolAddress((void**)&gcnt, g_counts);

    // CSR build (dst)
    cudaMemsetAsync(gcnt, 0, NN * sizeof(int));
    k_hist<<<(NE + 255) / 256, 256>>>(dst);
    int nsb = (NN + 1023) / 1024;
    k_scan1<<<nsb, 1024>>>();
    k_scan2<<<1, 64>>>(nsb);
    k_scan3<<<(NN + 255) / 256, 256>>>();
    k_scatter<<<(NE + 255) / 256, 256>>>(dst);

    // layer-1 node transforms (fused dual GEMM)
    dim3 gg((NN + 63) / 64, 2);
    k_gemm2<<<gg, 256>>>(x, W1l, b1l, W1r, b1r, gxl, gxr, NN);

    // layer-1 edges + ELU + layer-2 node transforms (fused)
    int nwb = (NN * 32 + 255) / 256;
    k_edge1<<<nwb, 256>>>(src, eattr, att1, W1e, b1e, bias1, W2l, b2l, W2r, b2r);

    // layer-2 edges, single pass
    k_edge2<<<nwb, 256>>>(src, eattr, W2e, b2e, att2, bias2, out);

    (void)in_sizes; (void)n_in; (void)out_size;
}

// round 7
// speedup vs baseline: 1.1606x; 1.0475x over previous
#include <cuda_runtime.h>
#include <cuda_bf16.h>
#include <math_constants.h>

#define NN 50000
#define NE 800000
#define NEG_SLOPE 0.2f

// ---------------- device scratch ----------------
__device__ float g_xl[(size_t)NN * 128];   // x @ W1l + b1l
__device__ float g_xr[(size_t)NN * 128];   // x @ W1r + b1r
__device__ float g_h2l[(size_t)NN * 8];    // h @ W2l + b2l (stride 8)
__device__ float g_h2r[(size_t)NN * 8];    // h @ W2r + b2r (stride 8)
__device__ int   g_counts[NN];
__device__ int   g_incl[NN + 1024];
__device__ int   g_off[NN + 1];
__device__ int   g_cursor[NN];
__device__ int   g_bsum[64];
__device__ int   g_eid[NE];

// ---------------- CSR build ----------------
__global__ void k_hist(const int* __restrict__ dst) {
    int i = blockIdx.x * blockDim.x + threadIdx.x;
    if (i < NE) atomicAdd(&g_counts[dst[i]], 1);
}

__global__ void k_scan1() {
    __shared__ int s[1024];
    int t = threadIdx.x;
    int idx = blockIdx.x * 1024 + t;
    int v = (idx < NN) ? g_counts[idx] : 0;
    s[t] = v;
    __syncthreads();
    #pragma unroll
    for (int o = 1; o < 1024; o <<= 1) {
        int add = (t >= o) ? s[t - o] : 0;
        __syncthreads();
        s[t] += add;
        __syncthreads();
    }
    g_incl[idx] = s[t];
    if (t == 1023) g_bsum[blockIdx.x] = s[1023];
}

__global__ void k_scan2(int nblocks) {
    __shared__ int s[64];
    int t = threadIdx.x;
    int v = (t < nblocks) ? g_bsum[t] : 0;
    s[t] = v;
    __syncthreads();
    #pragma unroll
    for (int o = 1; o < 64; o <<= 1) {
        int add = (t >= o) ? s[t - o] : 0;
        __syncthreads();
        s[t] += add;
        __syncthreads();
    }
    if (t < nblocks) g_bsum[t] = s[t] - v;   // exclusive
}

__global__ void k_scan3() {
    int i = blockIdx.x * blockDim.x + threadIdx.x;
    if (i < NN) {
        int incl = g_incl[i] + g_bsum[i / 1024];
        int excl = incl - g_counts[i];
        g_off[i] = excl;
        g_cursor[i] = excl;
        if (i == NN - 1) g_off[NN] = incl;
    }
}

__global__ void k_scatter(const int* __restrict__ dst) {
    int e = blockIdx.x * blockDim.x + threadIdx.x;
    if (e < NE) {
        int pos = atomicAdd(&g_cursor[dst[e]], 1);
        g_eid[pos] = e;
    }
}

// ---------------- fused dual GEMM: Cl = A@Bl+bl, Cr = A@Br+br ----------------
__global__ void k_gemm2(const float* __restrict__ A,
                        const float* __restrict__ Bl, const float* __restrict__ bl,
                        const float* __restrict__ Br, const float* __restrict__ br,
                        float* __restrict__ Cl, float* __restrict__ Cr, int M) {
    __shared__ float As [32][68];
    __shared__ float Bsl[32][68];
    __shared__ float Bsr[32][68];
    int tid = threadIdx.x;
    int tx = tid & 15, ty = tid >> 4;
    int rb = blockIdx.x * 64, cb = blockIdx.y * 64;
    float accl[4][4] = {}, accr[4][4] = {};

    int lr = tid >> 3;
    int lf = tid & 7;
    int bkr = tid >> 4;
    int bcq = tid & 15;

    for (int k0 = 0; k0 < 128; k0 += 32) {
        #pragma unroll
        for (int h = 0; h < 2; h++) {
            int r = lr + 32 * h;
            int gr = rb + r;
            float4 v = make_float4(0.f, 0.f, 0.f, 0.f);
            if (gr < M) v = *(const float4*)(A + (size_t)gr * 128 + k0 + lf * 4);
            As[lf * 4 + 0][r] = v.x;
            As[lf * 4 + 1][r] = v.y;
            As[lf * 4 + 2][r] = v.z;
            As[lf * 4 + 3][r] = v.w;
        }
        #pragma unroll
        for (int h = 0; h < 2; h++) {
            int kr = bkr + 16 * h;
            *(float4*)&Bsl[kr][bcq * 4] = *(const float4*)(Bl + (size_t)(k0 + kr) * 128 + cb + bcq * 4);
            *(float4*)&Bsr[kr][bcq * 4] = *(const float4*)(Br + (size_t)(k0 + kr) * 128 + cb + bcq * 4);
        }
        __syncthreads();
        #pragma unroll
        for (int kk = 0; kk < 32; kk++) {
            float4 a  = *(float4*)&As [kk][ty * 4];
            float4 vl = *(float4*)&Bsl[kk][tx * 4];
            float4 vr = *(float4*)&Bsr[kk][tx * 4];
            float av[4]  = {a.x, a.y, a.z, a.w};
            float blv[4] = {vl.x, vl.y, vl.z, vl.w};
            float brv[4] = {vr.x, vr.y, vr.z, vr.w};
            #pragma unroll
            for (int i = 0; i < 4; i++)
                #pragma unroll
                for (int j = 0; j < 4; j++) {
                    accl[i][j] += av[i] * blv[j];
                    accr[i][j] += av[i] * brv[j];
                }
        }
        __syncthreads();
    }
    #pragma unroll
    for (int i = 0; i < 4; i++) {
        int gr = rb + ty * 4 + i;
        if (gr < M) {
            #pragma unroll
            for (int j = 0; j < 4; j++) {
                int gc = cb + tx * 4 + j;
                Cl[(size_t)gr * 128 + gc] = accl[i][j] + bl[gc];
                Cr[(size_t)gr * 128 + gc] = accr[i][j] + br[gc];
            }
        }
    }
}

// ---------------- Layer-1 edges + ELU + layer-2 node transforms ----------------
// Warp per destination node. Edge PAIRS with 2-deep index prefetch and
// 1-deep value prefetch: L2 gather latency hidden behind shfl/exp chain.
__global__ void k_edge1(const int* __restrict__ src, const float* __restrict__ eattr,
                        const float* __restrict__ att1, const float* __restrict__ W1e,
                        const float* __restrict__ b1e, const float* __restrict__ bias1,
                        const float* __restrict__ W2l, const float* __restrict__ b2l,
                        const float* __restrict__ W2r, const float* __restrict__ b2r) {
    __shared__ float sWl[128 * 5], sWr[128 * 5];
    int tid = threadIdx.x;
    for (int i = tid; i < 640; i += blockDim.x) { sWl[i] = W2l[i]; sWr[i] = W2r[i]; }
    __syncthreads();

    int gw = (blockIdx.x * blockDim.x + tid) >> 5;
    int lane = tid & 31;
    if (gw >= NN) return;
    int n = gw;

    // xr folded with b1e (both added per edge, per channel)
    float xr0 = g_xr[(size_t)n * 128 + lane]      + __ldg(&b1e[lane]);
    float xr1 = g_xr[(size_t)n * 128 + lane + 32] + __ldg(&b1e[lane + 32]);
    float xr2 = g_xr[(size_t)n * 128 + lane + 64] + __ldg(&b1e[lane + 64]);
    float xr3 = g_xr[(size_t)n * 128 + lane + 96] + __ldg(&b1e[lane + 96]);
    float a0 = __ldg(&att1[lane]),      a1 = __ldg(&att1[lane + 32]);
    float a2 = __ldg(&att1[lane + 64]), a3 = __ldg(&att1[lane + 96]);
    float we0 = __ldg(&W1e[lane]),      we1 = __ldg(&W1e[lane + 32]);
    float we2 = __ldg(&W1e[lane + 64]), we3 = __ldg(&W1e[lane + 96]);

    int start = g_off[n], end = g_off[n + 1];
    int deg = end - start;
    int np = (deg + 1) >> 1;     // number of edge pairs

    float m0 = -CUDART_INF_F, m1 = -CUDART_INF_F;
    float d0 = 0.f, d1 = 0.f;
    float A0 = 0.f, A1 = 0.f, A2 = 0.f, A3 = 0.f;

#define LOAD_IDX(j, sa, sb, ea, eb, hb) do {                          \
        int _i0 = start + 2 * (j);                                    \
        int _e0 = __ldg(&g_eid[_i0]);                                 \
        (hb) = (2 * (j) + 1 < deg);                                   \
        int _e1 = (hb) ? __ldg(&g_eid[_i0 + 1]) : _e0;                \
        (sa) = __ldg(&src[_e0]); (ea) = __ldg(&eattr[_e0]);           \
        (sb) = __ldg(&src[_e1]); (eb) = __ldg(&eattr[_e1]);           \
    } while (0)

#define LOAD_VAL(sa, sb, xa, xb) do {                                 \
        size_t _ba = (size_t)(sa) * 128 + lane;                       \
        size_t _bb = (size_t)(sb) * 128 + lane;                       \
        (xa)[0] = g_xl[_ba];      (xa)[1] = g_xl[_ba + 32];           \
        (xa)[2] = g_xl[_ba + 64]; (xa)[3] = g_xl[_ba + 96];           \
        (xb)[0] = g_xl[_bb];      (xb)[1] = g_xl[_bb + 32];           \
        (xb)[2] = g_xl[_bb + 64]; (xb)[3] = g_xl[_bb + 96];           \
    } while (0)

    int sa0 = 0, sb0 = 0, hb0 = 0;  float ea0 = 0.f, eb0 = 0.f;
    int sa1 = 0, sb1 = 0, hb1 = 0;  float ea1 = 0.f, eb1 = 0.f;
    float xa[4], xb[4];

    if (np > 0) { LOAD_IDX(0, sa0, sb0, ea0, eb0, hb0); LOAD_VAL(sa0, sb0, xa, xb); }
    if (np > 1) LOAD_IDX(1, sa1, sb1, ea1, eb1, hb1);

    for (int j = 0; j < np; j++) {
        // prefetch values for pair j+1 and indices for pair j+2
        float nxa[4], nxb[4];
        if (j + 1 < np) LOAD_VAL(sa1, sb1, nxa, nxb);
        int nsa = 0, nsb = 0, nhb = 0; float nea = 0.f, neb = 0.f;
        if (j + 2 < np) LOAD_IDX(j + 2, nsa, nsb, nea, neb, nhb);

        // compute both edges of current pair
        float ta0 = xa[0] + xr0 + ea0 * we0;
        float ta1 = xa[1] + xr1 + ea0 * we1;
        float ta2 = xa[2] + xr2 + ea0 * we2;
        float ta3 = xa[3] + xr3 + ea0 * we3;
        float tb0 = xb[0] + xr0 + eb0 * we0;
        float tb1 = xb[1] + xr1 + eb0 * we1;
        float tb2 = xb[2] + xr2 + eb0 * we2;
        float tb3 = xb[3] + xr3 + eb0 * we3;
        ta0 = ta0 > 0.f ? ta0 : NEG_SLOPE * ta0;
        ta1 = ta1 > 0.f ? ta1 : NEG_SLOPE * ta1;
        ta2 = ta2 > 0.f ? ta2 : NEG_SLOPE * ta2;
        ta3 = ta3 > 0.f ? ta3 : NEG_SLOPE * ta3;
        tb0 = tb0 > 0.f ? tb0 : NEG_SLOPE * tb0;
        tb1 = tb1 > 0.f ? tb1 : NEG_SLOPE * tb1;
        tb2 = tb2 > 0.f ? tb2 : NEG_SLOPE * tb2;
        tb3 = tb3 > 0.f ? tb3 : NEG_SLOPE * tb3;
        float pa0 = ta0 * a0 + ta1 * a1;
        float pa1 = ta2 * a2 + ta3 * a3;
        float pb0 = tb0 * a0 + tb1 * a1;
        float pb1 = tb2 * a2 + tb3 * a3;
        #pragma unroll
        for (int o = 16; o > 0; o >>= 1) {
            pa0 += __shfl_xor_sync(0xffffffffu, pa0, o);
            pa1 += __shfl_xor_sync(0xffffffffu, pa1, o);
            pb0 += __shfl_xor_sync(0xffffffffu, pb0, o);
            pb1 += __shfl_xor_sync(0xffffffffu, pb1, o);
        }
        if (!hb0) { pb0 = -CUDART_INF_F; pb1 = -CUDART_INF_F; }

        // merge edge a (always valid)
        {
            float nm = fmaxf(m0, pa0);
            float corr = __expf(m0 - nm);
            float w = __expf(pa0 - nm);
            d0 = d0 * corr + w;
            A0 = A0 * corr + w * xa[0];
            A1 = A1 * corr + w * xa[1];
            m0 = nm;
        }
        {
            float nm = fmaxf(m1, pa1);
            float corr = __expf(m1 - nm);
            float w = __expf(pa1 - nm);
            d1 = d1 * corr + w;
            A2 = A2 * corr + w * xa[2];
            A3 = A3 * corr + w * xa[3];
            m1 = nm;
        }
        // merge edge b (w=0 no-op when !hb0; m0/m1 finite after edge a)
        {
            float nm = fmaxf(m0, pb0);
            float corr = __expf(m0 - nm);
            float w = __expf(pb0 - nm);
            d0 = d0 * corr + w;
            A0 = A0 * corr + w * xb[0];
            A1 = A1 * corr + w * xb[1];
            m0 = nm;
        }
        {
            float nm = fmaxf(m1, pb1);
            float corr = __expf(m1 - nm);
            float w = __expf(pb1 - nm);
            d1 = d1 * corr + w;
            A2 = A2 * corr + w * xb[2];
            A3 = A3 * corr + w * xb[3];
            m1 = nm;
        }

        // rotate pipeline registers
        #pragma unroll
        for (int c = 0; c < 4; c++) { xa[c] = nxa[c]; xb[c] = nxb[c]; }
        ea0 = ea1; eb0 = eb1; hb0 = hb1;
        sa1 = nsa; sb1 = nsb; ea1 = nea; eb1 = neb; hb1 = nhb;
    }
#undef LOAD_IDX
#undef LOAD_VAL

    float o0 = (d0 > 0.f) ? A0 / d0 : 0.f;
    float o1 = (d0 > 0.f) ? A1 / d0 : 0.f;
    float o2 = (d1 > 0.f) ? A2 / d1 : 0.f;
    float o3 = (d1 > 0.f) ? A3 / d1 : 0.f;
    o0 += __ldg(&bias1[lane]);
    o1 += __ldg(&bias1[lane + 32]);
    o2 += __ldg(&bias1[lane + 64]);
    o3 += __ldg(&bias1[lane + 96]);
    o0 = o0 > 0.f ? o0 : (__expf(o0) - 1.f);
    o1 = o1 > 0.f ? o1 : (__expf(o1) - 1.f);
    o2 = o2 > 0.f ? o2 : (__expf(o2) - 1.f);
    o3 = o3 > 0.f ? o3 : (__expf(o3) - 1.f);

    // layer-2 node transforms
    float hv[4] = {o0, o1, o2, o3};
    #pragma unroll
    for (int c = 0; c < 5; c++) {
        float pl = 0.f, pr = 0.f;
        #pragma unroll
        for (int j = 0; j < 4; j++) {
            int k = lane + 32 * j;
            pl += hv[j] * sWl[k * 5 + c];
            pr += hv[j] * sWr[k * 5 + c];
        }
        #pragma unroll
        for (int o = 16; o > 0; o >>= 1) {
            pl += __shfl_xor_sync(0xffffffffu, pl, o);
            pr += __shfl_xor_sync(0xffffffffu, pr, o);
        }
        if (lane == 0) {
            g_h2l[(size_t)n * 8 + c] = pl + __ldg(&b2l[c]);
            g_h2r[(size_t)n * 8 + c] = pr + __ldg(&b2r[c]);
        }
    }
}

// ---------------- Layer-2 edge phase ----------------
__global__ void k_edge2(const int* __restrict__ src, const float* __restrict__ eattr,
                        const float* __restrict__ W2e, const float* __restrict__ b2e,
                        const float* __restrict__ att2, const float* __restrict__ bias2,
                        float* __restrict__ out) {
    int gw = (blockIdx.x * blockDim.x + threadIdx.x) >> 5;
    int lane = threadIdx.x & 31;
    if (gw >= NN) return;
    int n = gw;

    float xr[5], a2[5], we[5], be[5];
    #pragma unroll
    for (int c = 0; c < 5; c++) {
        xr[c] = g_h2r[(size_t)n * 8 + c];
        a2[c] = __ldg(&att2[c]);
        we[c] = __ldg(&W2e[c]);
        be[c] = __ldg(&b2e[c]);
    }
    int off0 = g_off[n];
    int deg = g_off[n + 1] - off0;

    float m = -CUDART_INF_F, d = 0.f, ac[5] = {0.f, 0.f, 0.f, 0.f, 0.f};
    for (int i = lane; i < deg; i += 32) {
        int e = __ldg(&g_eid[off0 + i]);
        int s = __ldg(&src[e]);
        float ea = __ldg(&eattr[e]);
        const float* xl = &g_h2l[(size_t)s * 8];
        float lg = 0.f, xlv[5];
        #pragma unroll
        for (int c = 0; c < 5; c++) {
            xlv[c] = xl[c];
            float t = xlv[c] + xr[c] + ea * we[c] + be[c];
            t = t > 0.f ? t : NEG_SLOPE * t;
            lg += a2[c] * t;
        }
        float nm = fmaxf(m, lg);
        float corr = __expf(m - nm);
        float w = __expf(lg - nm);
        d = d * corr + w;
        #pragma unroll
        for (int c = 0; c < 5; c++) ac[c] = ac[c] * corr + w * xlv[c];
        m = nm;
    }
    float M = m;
    #pragma unroll
    for (int o = 16; o > 0; o >>= 1)
        M = fmaxf(M, __shfl_xor_sync(0xffffffffu, M, o));
    float sc = (m == -CUDART_INF_F) ? 0.f : __expf(m - M);
    d *= sc;
    #pragma unroll
    for (int c = 0; c < 5; c++) ac[c] *= sc;
    #pragma unroll
    for (int o = 16; o > 0; o >>= 1) {
        d += __shfl_xor_sync(0xffffffffu, d, o);
        #pragma unroll
        for (int c = 0; c < 5; c++) ac[c] += __shfl_xor_sync(0xffffffffu, ac[c], o);
    }
    if (lane == 0) {
        #pragma unroll
        for (int c = 0; c < 5; c++) {
            float v = (d > 0.f) ? ac[c] / d : 0.f;
            out[(size_t)n * 5 + c] = v + __ldg(&bias2[c]);
        }
    }
}

// ---------------- launch: CSR build || GEMM via fork-join streams ----------------
extern "C" void kernel_launch(void* const* d_in, const int* in_sizes, int n_in,
                              void* d_out, int out_size) {
    const float* x     = (const float*)d_in[0];
    const int*   eidx  = (const int*)d_in[1];
    const float* eattr = (const float*)d_in[2];
    const float* W1l   = (const float*)d_in[3];
    const float* b1l   = (const float*)d_in[4];
    const float* W1r   = (const float*)d_in[5];
    const float* b1r   = (const float*)d_in[6];
    const float* W1e   = (const float*)d_in[7];
    const float* b1e   = (const float*)d_in[8];
    const float* att1  = (const float*)d_in[9];
    const float* bias1 = (const float*)d_in[10];
    const float* W2l   = (const float*)d_in[11];
    const float* b2l   = (const float*)d_in[12];
    const float* W2r   = (const float*)d_in[13];
    const float* b2r   = (const float*)d_in[14];
    const float* W2e   = (const float*)d_in[15];
    const float* b2e   = (const float*)d_in[16];
    const float* att2  = (const float*)d_in[17];
    const float* bias2 = (const float*)d_in[18];
    float* out = (float*)d_out;

    const int* src = eidx;
    const int* dst = eidx + NE;

    float* gxl; cudaGetSymbolAddress((void**)&gxl, g_xl);
    float* gxr; cudaGetSymbolAddress((void**)&gxr, g_xr);
    int* gcnt;  cudaGetSymbolAddress((void**)&gcnt, g_counts);

    // fork: GEMM runs on a side stream concurrently with the CSR build
    cudaStream_t s2;
    cudaStreamCreateWithFlags(&s2, cudaStreamNonBlocking);
    cudaEvent_t ef, ej;
    cudaEventCreateWithFlags(&ef, cudaEventDisableTiming);
    cudaEventCreateWithFlags(&ej, cudaEventDisableTiming);

    cudaEventRecord(ef, 0);
    cudaStreamWaitEvent(s2, ef, 0);
    dim3 gg((NN + 63) / 64, 2);
    k_gemm2<<<gg, 256, 0, s2>>>(x, W1l, b1l, W1r, b1r, gxl, gxr, NN);
    cudaEventRecord(ej, s2);

    // CSR build on the main stream (concurrent with GEMM)
    cudaMemsetAsync(gcnt, 0, NN * sizeof(int));
    k_hist<<<(NE + 255) / 256, 256>>>(dst);
    int nsb = (NN + 1023) / 1024;
    k_scan1<<<nsb, 1024>>>();
    k_scan2<<<1, 64>>>(nsb);
    k_scan3<<<(NN + 255) / 256, 256>>>();
    k_scatter<<<(NE + 255) / 256, 256>>>(dst);

    // join
    cudaStreamWaitEvent(0, ej, 0);

    int nwb = (NN * 32 + 255) / 256;
    k_edge1<<<nwb, 256>>>(src, eattr, att1, W1e, b1e, bias1, W2l, b2l, W2r, b2r);
    k_edge2<<<nwb, 256>>>(src, eattr, W2e, b2e, att2, bias2, out);

    cudaEventDestroy(ef);
    cudaEventDestroy(ej);
    cudaStreamDestroy(s2);

    (void)in_sizes; (void)n_in; (void)out_size;
}

// round 9
// speedup vs baseline: 1.2575x; 1.0834x over previous
#include <cuda_runtime.h>
#include <cuda_bf16.h>
#include <math_constants.h>

#define NN 50000
#define NE 800000
#define NEG_SLOPE 0.2f

// ---------------- device scratch ----------------
__device__ float g_xl[(size_t)NN * 128];   // x @ W1l + b1l
__device__ float g_xr[(size_t)NN * 128];   // x @ W1r + b1r
__device__ float g_h2l[(size_t)NN * 8];    // h @ W2l + b2l (stride 8)
__device__ float g_h2r[(size_t)NN * 8];    // h @ W2r + b2r (stride 8)
__device__ float g_Bcat[128 * 256];        // [k][c]: c<128 -> W1l, else W1r
__device__ float g_bcat[256];
__device__ int   g_counts[NN];
__device__ int   g_incl[NN + 1024];
__device__ int   g_off[NN + 1];
__device__ int   g_cursor[NN];
__device__ int   g_bsum[64];
__device__ int   g_esrc[NE];               // CSR payload: source node
__device__ float g_eea[NE];                // CSR payload: edge attr

// ---------------- CSR build ----------------
__global__ void k_hist(const int* __restrict__ dst) {
    int i = blockIdx.x * blockDim.x + threadIdx.x;
    if (i < NE) atomicAdd(&g_counts[dst[i]], 1);
}

__global__ void k_scan1() {
    __shared__ int s[1024];
    int t = threadIdx.x;
    int idx = blockIdx.x * 1024 + t;
    int v = (idx < NN) ? g_counts[idx] : 0;
    s[t] = v;
    __syncthreads();
    #pragma unroll
    for (int o = 1; o < 1024; o <<= 1) {
        int add = (t >= o) ? s[t - o] : 0;
        __syncthreads();
        s[t] += add;
        __syncthreads();
    }
    g_incl[idx] = s[t];
    if (t == 1023) g_bsum[blockIdx.x] = s[1023];
}

__global__ void k_scan2(int nblocks) {
    __shared__ int s[64];
    int t = threadIdx.x;
    int v = (t < nblocks) ? g_bsum[t] : 0;
    s[t] = v;
    __syncthreads();
    #pragma unroll
    for (int o = 1; o < 64; o <<= 1) {
        int add = (t >= o) ? s[t - o] : 0;
        __syncthreads();
        s[t] += add;
        __syncthreads();
    }
    if (t < nblocks) g_bsum[t] = s[t] - v;   // exclusive
}

__global__ void k_scan3() {
    int i = blockIdx.x * blockDim.x + threadIdx.x;
    if (i < NN) {
        int incl = g_incl[i] + g_bsum[i / 1024];
        int excl = incl - g_counts[i];
        g_off[i] = excl;
        g_cursor[i] = excl;
        if (i == NN - 1) g_off[NN] = incl;
    }
}

__global__ void k_scatter(const int* __restrict__ dst, const int* __restrict__ src,
                          const float* __restrict__ ea) {
    int e = blockIdx.x * blockDim.x + threadIdx.x;
    if (e < NE) {
        int pos = atomicAdd(&g_cursor[dst[e]], 1);
        g_esrc[pos] = src[e];
        g_eea[pos] = ea[e];
    }
}

// ---------------- pack W1l|W1r into Bcat [128,256] ----------------
__global__ void k_pack(const float* __restrict__ Bl, const float* __restrict__ bl,
                       const float* __restrict__ Br, const float* __restrict__ br) {
    int i = blockIdx.x * blockDim.x + threadIdx.x;
    if (i < 128 * 256) {
        int k = i >> 8, c = i & 255;
        g_Bcat[i] = (c < 128) ? Bl[k * 128 + c] : Br[k * 128 + (c - 128)];
    }
    if (i < 256) g_bcat[i] = (i < 128) ? bl[i] : br[i - 128];
}

// ---------------- SGEMM: 128x128 block, 8x8 per thread ----------------
// grid (ceil(M/128), 2): blockIdx.y selects output matrix (Cl / Cr).
__global__ __launch_bounds__(256, 2)
void k_gemm3(const float* __restrict__ A, float* __restrict__ Cl,
             float* __restrict__ Cr, int M) {
    __shared__ float As[32][132];   // [k][m]
    __shared__ float Bs[32][132];   // [k][n]
    int tid = threadIdx.x;
    int tx = tid & 15, ty = tid >> 4;
    int rb = blockIdx.x * 128;
    int cbase = blockIdx.y * 128;
    float acc[8][8] = {};

    for (int k0 = 0; k0 < 128; k0 += 32) {
        #pragma unroll
        for (int u = 0; u < 4; u++) {
            int idx = tid + 256 * u;         // 0..1023
            int r = idx >> 3;                // 8 float4 per A row
            int c4 = idx & 7;
            int gr = rb + r;
            float4 v = make_float4(0.f, 0.f, 0.f, 0.f);
            if (gr < M) v = *(const float4*)(A + (size_t)gr * 128 + k0 + c4 * 4);
            As[c4 * 4 + 0][r] = v.x;
            As[c4 * 4 + 1][r] = v.y;
            As[c4 * 4 + 2][r] = v.z;
            As[c4 * 4 + 3][r] = v.w;
        }
        #pragma unroll
        for (int u = 0; u < 4; u++) {
            int idx = tid + 256 * u;
            int r = idx >> 5;                // 32 float4 per B row
            int c4 = idx & 31;
            *(float4*)&Bs[r][c4 * 4] =
                *(const float4*)(g_Bcat + (size_t)(k0 + r) * 256 + cbase + c4 * 4);
        }
        __syncthreads();
        #pragma unroll
        for (int kk = 0; kk < 32; kk++) {
            float a[8], b[8];
            *(float4*)&a[0] = *(float4*)&As[kk][ty * 8];
            *(float4*)&a[4] = *(float4*)&As[kk][ty * 8 + 4];
            *(float4*)&b[0] = *(float4*)&Bs[kk][tx * 8];
            *(float4*)&b[4] = *(float4*)&Bs[kk][tx * 8 + 4];
            #pragma unroll
            for (int i = 0; i < 8; i++)
                #pragma unroll
                for (int j = 0; j < 8; j++)
                    acc[i][j] += a[i] * b[j];
        }
        __syncthreads();
    }

    float* C = (blockIdx.y == 0) ? Cl : Cr;
    #pragma unroll
    for (int i = 0; i < 8; i++) {
        int gr = rb + ty * 8 + i;
        if (gr < M) {
            #pragma unroll
            for (int jq = 0; jq < 2; jq++) {
                int c = tx * 8 + jq * 4;
                float4 v;
                v.x = acc[i][jq * 4 + 0] + g_bcat[cbase + c + 0];
                v.y = acc[i][jq * 4 + 1] + g_bcat[cbase + c + 1];
                v.z = acc[i][jq * 4 + 2] + g_bcat[cbase + c + 2];
                v.w = acc[i][jq * 4 + 3] + g_bcat[cbase + c + 3];
                *(float4*)(C + (size_t)gr * 128 + c) = v;
            }
        }
    }
}

// ---------------- Layer-1 edges + ELU + layer-2 node transforms ----------------
__global__ void k_edge1(const float* __restrict__ att1, const float* __restrict__ W1e,
                        const float* __restrict__ b1e, const float* __restrict__ bias1,
                        const float* __restrict__ W2l, const float* __restrict__ b2l,
                        const float* __restrict__ W2r, const float* __restrict__ b2r) {
    __shared__ float sWl[128 * 5], sWr[128 * 5];
    int tid = threadIdx.x;
    for (int i = tid; i < 640; i += blockDim.x) { sWl[i] = W2l[i]; sWr[i] = W2r[i]; }
    __syncthreads();

    int gw = (blockIdx.x * blockDim.x + tid) >> 5;
    int lane = tid & 31;
    if (gw >= NN) return;
    int n = gw;

    float xr0 = g_xr[(size_t)n * 128 + lane]      + __ldg(&b1e[lane]);
    float xr1 = g_xr[(size_t)n * 128 + lane + 32] + __ldg(&b1e[lane + 32]);
    float xr2 = g_xr[(size_t)n * 128 + lane + 64] + __ldg(&b1e[lane + 64]);
    float xr3 = g_xr[(size_t)n * 128 + lane + 96] + __ldg(&b1e[lane + 96]);
    float a0 = __ldg(&att1[lane]),      a1 = __ldg(&att1[lane + 32]);
    float a2 = __ldg(&att1[lane + 64]), a3 = __ldg(&att1[lane + 96]);
    float we0 = __ldg(&W1e[lane]),      we1 = __ldg(&W1e[lane + 32]);
    float we2 = __ldg(&W1e[lane + 64]), we3 = __ldg(&W1e[lane + 96]);

    int start = g_off[n], end = g_off[n + 1];
    int deg = end - start;
    int np = (deg + 1) >> 1;

    float m0 = -CUDART_INF_F, m1 = -CUDART_INF_F;
    float d0 = 0.f, d1 = 0.f;
    float A0 = 0.f, A1 = 0.f, A2 = 0.f, A3 = 0.f;

#define LOAD_IDX(j, sa, sb, ea, eb, hb) do {                          \
        int _i0 = start + 2 * (j);                                    \
        (sa) = __ldg(&g_esrc[_i0]); (ea) = __ldg(&g_eea[_i0]);        \
        (hb) = (2 * (j) + 1 < deg);                                   \
        (sb) = (hb) ? __ldg(&g_esrc[_i0 + 1]) : (sa);                 \
        (eb) = (hb) ? __ldg(&g_eea[_i0 + 1]) : (ea);                  \
    } while (0)

#define LOAD_VAL(sa, sb, xa, xb) do {                                 \
        size_t _ba = (size_t)(sa) * 128 + lane;                       \
        size_t _bb = (size_t)(sb) * 128 + lane;                       \
        (xa)[0] = g_xl[_ba];      (xa)[1] = g_xl[_ba + 32];           \
        (xa)[2] = g_xl[_ba + 64]; (xa)[3] = g_xl[_ba + 96];           \
        (xb)[0] = g_xl[_bb];      (xb)[1] = g_xl[_bb + 32];           \
        (xb)[2] = g_xl[_bb + 64]; (xb)[3] = g_xl[_bb + 96];           \
    } while (0)

    int sa0 = 0, sb0 = 0, hb0 = 0;  float ea0 = 0.f, eb0 = 0.f;
    int sa1 = 0, sb1 = 0, hb1 = 0;  float ea1 = 0.f, eb1 = 0.f;
    float xa[4], xb[4];

    if (np > 0) { LOAD_IDX(0, sa0, sb0, ea0, eb0, hb0); LOAD_VAL(sa0, sb0, xa, xb); }
    if (np > 1) LOAD_IDX(1, sa1, sb1, ea1, eb1, hb1);

    for (int j = 0; j < np; j++) {
        float nxa[4], nxb[4];
        if (j + 1 < np) LOAD_VAL(sa1, sb1, nxa, nxb);
        int nsa = 0, nsb = 0, nhb = 0; float nea = 0.f, neb = 0.f;
        if (j + 2 < np) LOAD_IDX(j + 2, nsa, nsb, nea, neb, nhb);

        float ta0 = xa[0] + xr0 + ea0 * we0;
        float ta1 = xa[1] + xr1 + ea0 * we1;
        float ta2 = xa[2] + xr2 + ea0 * we2;
        float ta3 = xa[3] + xr3 + ea0 * we3;
        float tb0 = xb[0] + xr0 + eb0 * we0;
        float tb1 = xb[1] + xr1 + eb0 * we1;
        float tb2 = xb[2] + xr2 + eb0 * we2;
        float tb3 = xb[3] + xr3 + eb0 * we3;
        ta0 = ta0 > 0.f ? ta0 : NEG_SLOPE * ta0;
        ta1 = ta1 > 0.f ? ta1 : NEG_SLOPE * ta1;
        ta2 = ta2 > 0.f ? ta2 : NEG_SLOPE * ta2;
        ta3 = ta3 > 0.f ? ta3 : NEG_SLOPE * ta3;
        tb0 = tb0 > 0.f ? tb0 : NEG_SLOPE * tb0;
        tb1 = tb1 > 0.f ? tb1 : NEG_SLOPE * tb1;
        tb2 = tb2 > 0.f ? tb2 : NEG_SLOPE * tb2;
        tb3 = tb3 > 0.f ? tb3 : NEG_SLOPE * tb3;
        float pa0 = ta0 * a0 + ta1 * a1;
        float pa1 = ta2 * a2 + ta3 * a3;
        float pb0 = tb0 * a0 + tb1 * a1;
        float pb1 = tb2 * a2 + tb3 * a3;
        #pragma unroll
        for (int o = 16; o > 0; o >>= 1) {
            pa0 += __shfl_xor_sync(0xffffffffu, pa0, o);
            pa1 += __shfl_xor_sync(0xffffffffu, pa1, o);
            pb0 += __shfl_xor_sync(0xffffffffu, pb0, o);
            pb1 += __shfl_xor_sync(0xffffffffu, pb1, o);
        }
        if (!hb0) { pb0 = -CUDART_INF_F; pb1 = -CUDART_INF_F; }

        {
            float nm = fmaxf(m0, pa0);
            float corr = __expf(m0 - nm);
            float w = __expf(pa0 - nm);
            d0 = d0 * corr + w;
            A0 = A0 * corr + w * xa[0];
            A1 = A1 * corr + w * xa[1];
            m0 = nm;
        }
        {
            float nm = fmaxf(m1, pa1);
            float corr = __expf(m1 - nm);
            float w = __expf(pa1 - nm);
            d1 = d1 * corr + w;
            A2 = A2 * corr + w * xa[2];
            A3 = A3 * corr + w * xa[3];
            m1 = nm;
        }
        {
            float nm = fmaxf(m0, pb0);
            float corr = __expf(m0 - nm);
            float w = __expf(pb0 - nm);
            d0 = d0 * corr + w;
            A0 = A0 * corr + w * xb[0];
            A1 = A1 * corr + w * xb[1];
            m0 = nm;
        }
        {
            float nm = fmaxf(m1, pb1);
            float corr = __expf(m1 - nm);
            float w = __expf(pb1 - nm);
            d1 = d1 * corr + w;
            A2 = A2 * corr + w * xb[2];
            A3 = A3 * corr + w * xb[3];
            m1 = nm;
        }

        #pragma unroll
        for (int c = 0; c < 4; c++) { xa[c] = nxa[c]; xb[c] = nxb[c]; }
        ea0 = ea1; eb0 = eb1; hb0 = hb1;
        sa1 = nsa; sb1 = nsb; ea1 = nea; eb1 = neb; hb1 = nhb;
    }
#undef LOAD_IDX
#undef LOAD_VAL

    float o0 = (d0 > 0.f) ? A0 / d0 : 0.f;
    float o1 = (d0 > 0.f) ? A1 / d0 : 0.f;
    float o2 = (d1 > 0.f) ? A2 / d1 : 0.f;
    float o3 = (d1 > 0.f) ? A3 / d1 : 0.f;
    o0 += __ldg(&bias1[lane]);
    o1 += __ldg(&bias1[lane + 32]);
    o2 += __ldg(&bias1[lane + 64]);
    o3 += __ldg(&bias1[lane + 96]);
    o0 = o0 > 0.f ? o0 : (__expf(o0) - 1.f);
    o1 = o1 > 0.f ? o1 : (__expf(o1) - 1.f);
    o2 = o2 > 0.f ? o2 : (__expf(o2) - 1.f);
    o3 = o3 > 0.f ? o3 : (__expf(o3) - 1.f);

    float hv[4] = {o0, o1, o2, o3};
    #pragma unroll
    for (int c = 0; c < 5; c++) {
        float pl = 0.f, pr = 0.f;
        #pragma unroll
        for (int j = 0; j < 4; j++) {
            int k = lane + 32 * j;
            pl += hv[j] * sWl[k * 5 + c];
            pr += hv[j] * sWr[k * 5 + c];
        }
        #pragma unroll
        for (int o = 16; o > 0; o >>= 1) {
            pl += __shfl_xor_sync(0xffffffffu, pl, o);
            pr += __shfl_xor_sync(0xffffffffu, pr, o);
        }
        if (lane == 0) {
            g_h2l[(size_t)n * 8 + c] = pl + __ldg(&b2l[c]);
            g_h2r[(size_t)n * 8 + c] = pr + __ldg(&b2r[c]);
        }
    }
}

// ---------------- Layer-2 edge phase ----------------
__global__ void k_edge2(const float* __restrict__ W2e, const float* __restrict__ b2e,
                        const float* __restrict__ att2, const float* __restrict__ bias2,
                        float* __restrict__ out) {
    int gw = (blockIdx.x * blockDim.x + threadIdx.x) >> 5;
    int lane = threadIdx.x & 31;
    if (gw >= NN) return;
    int n = gw;

    float xr[5], a2[5], we[5], be[5];
    #pragma unroll
    for (int c = 0; c < 5; c++) {
        xr[c] = g_h2r[(size_t)n * 8 + c];
        a2[c] = __ldg(&att2[c]);
        we[c] = __ldg(&W2e[c]);
        be[c] = __ldg(&b2e[c]);
    }
    int off0 = g_off[n];
    int deg = g_off[n + 1] - off0;

    float m = -CUDART_INF_F, d = 0.f, ac[5] = {0.f, 0.f, 0.f, 0.f, 0.f};
    for (int i = lane; i < deg; i += 32) {
        int s = __ldg(&g_esrc[off0 + i]);
        float ea = __ldg(&g_eea[off0 + i]);
        float4 v4 = *(const float4*)&g_h2l[(size_t)s * 8];
        float x4 = g_h2l[(size_t)s * 8 + 4];
        float xlv[5] = {v4.x, v4.y, v4.z, v4.w, x4};
        float lg = 0.f;
        #pragma unroll
        for (int c = 0; c < 5; c++) {
            float t = xlv[c] + xr[c] + ea * we[c] + be[c];
            t = t > 0.f ? t : NEG_SLOPE * t;
            lg += a2[c] * t;
        }
        float nm = fmaxf(m, lg);
        float corr = __expf(m - nm);
        float w = __expf(lg - nm);
        d = d * corr + w;
        #pragma unroll
        for (int c = 0; c < 5; c++) ac[c] = ac[c] * corr + w * xlv[c];
        m = nm;
    }
    float M = m;
    #pragma unroll
    for (int o = 16; o > 0; o >>= 1)
        M = fmaxf(M, __shfl_xor_sync(0xffffffffu, M, o));
    float sc = (m == -CUDART_INF_F) ? 0.f : __expf(m - M);
    d *= sc;
    #pragma unroll
    for (int c = 0; c < 5; c++) ac[c] *= sc;
    #pragma unroll
    for (int o = 16; o > 0; o >>= 1) {
        d += __shfl_xor_sync(0xffffffffu, d, o);
        #pragma unroll
        for (int c = 0; c < 5; c++) ac[c] += __shfl_xor_sync(0xffffffffu, ac[c], o);
    }
    if (lane == 0) {
        #pragma unroll
        for (int c = 0; c < 5; c++) {
            float v = (d > 0.f) ? ac[c] / d : 0.f;
            out[(size_t)n * 5 + c] = v + __ldg(&bias2[c]);
        }
    }
}

// ---------------- launch: CSR build || (pack+GEMM) via fork-join ----------------
extern "C" void kernel_launch(void* const* d_in, const int* in_sizes, int n_in,
                              void* d_out, int out_size) {
    const float* x     = (const float*)d_in[0];
    const int*   eidx  = (const int*)d_in[1];
    const float* eattr = (const float*)d_in[2];
    const float* W1l   = (const float*)d_in[3];
    const float* b1l   = (const float*)d_in[4];
    const float* W1r   = (const float*)d_in[5];
    const float* b1r   = (const float*)d_in[6];
    const float* W1e   = (const float*)d_in[7];
    const float* b1e   = (const float*)d_in[8];
    const float* att1  = (const float*)d_in[9];
    const float* bias1 = (const float*)d_in[10];
    const float* W2l   = (const float*)d_in[11];
    const float* b2l   = (const float*)d_in[12];
    const float* W2r   = (const float*)d_in[13];
    const float* b2r   = (const float*)d_in[14];
    const float* W2e   = (const float*)d_in[15];
    const float* b2e   = (const float*)d_in[16];
    const float* att2  = (const float*)d_in[17];
    const float* bias2 = (const float*)d_in[18];
    float* out = (float*)d_out;

    const int* src = eidx;
    const int* dst = eidx + NE;

    float* gxl; cudaGetSymbolAddress((void**)&gxl, g_xl);
    float* gxr; cudaGetSymbolAddress((void**)&gxr, g_xr);
    int* gcnt;  cudaGetSymbolAddress((void**)&gcnt, g_counts);

    cudaStream_t s2;
    cudaStreamCreateWithFlags(&s2, cudaStreamNonBlocking);
    cudaEvent_t ef, ej;
    cudaEventCreateWithFlags(&ef, cudaEventDisableTiming);
    cudaEventCreateWithFlags(&ej, cudaEventDisableTiming);

    // fork: pack + GEMM on side stream
    cudaEventRecord(ef, 0);
    cudaStreamWaitEvent(s2, ef, 0);
    k_pack<<<128, 256, 0, s2>>>(W1l, b1l, W1r, b1r);
    dim3 gg((NN + 127) / 128, 2);
    k_gemm3<<<gg, 256, 0, s2>>>(x, gxl, gxr, NN);
    cudaEventRecord(ej, s2);

    // CSR build on the main stream (concurrent with GEMM)
    cudaMemsetAsync(gcnt, 0, NN * sizeof(int));
    k_hist<<<(NE + 255) / 256, 256>>>(dst);
    int nsb = (NN + 1023) / 1024;
    k_scan1<<<nsb, 1024>>>();
    k_scan2<<<1, 64>>>(nsb);
    k_scan3<<<(NN + 255) / 256, 256>>>();
    k_scatter<<<(NE + 255) / 256, 256>>>(dst, src, eattr);

    // join
    cudaStreamWaitEvent(0, ej, 0);

    int nwb = (NN * 32 + 255) / 256;
    k_edge1<<<nwb, 256>>>(att1, W1e, b1e, bias1, W2l, b2l, W2r, b2r);
    k_edge2<<<nwb, 256>>>(W2e, b2e, att2, bias2, out);

    cudaEventDestroy(ef);
    cudaEventDestroy(ej);
    cudaStreamDestroy(s2);

    (void)in_sizes; (void)n_in; (void)out_size;
}